// round 1
// baseline (speedup 1.0000x reference)
#include <cuda_runtime.h>
#include <cuda_bf16.h>
#include <cstdint>

// Problem constants
#define BSZ   4096
#define CDIM  128
#define TOPK  8
#define NSUP  (BSZ*TOPK)     // 32768 support rows
#define PIDS  256            // identity blocks
#define BLKC  128            // columns per identity block (K_INST*TOPK)
#define NSPLIT 4
#define BLOCKS_PER_SPLIT (PIDS/NSPLIT)   // 64
#define MTILE 128
#define MTILES (BSZ/MTILE)   // 32
#define INV_TEMP 20.0f
#define EPSV 1e-6f
#define SROW 136             // smem row stride in bf16 (128 + 8 pad, 16B-aligned rows, conflict-free)

// Scratch (static device globals: no allocation at runtime)
__device__ __nv_bfloat16 g_fs_bf[(size_t)NSUP * CDIM];       // 8 MB
__device__ float g_negpart[NSPLIT * BSZ];
__device__ float g_pospart[NSPLIT * BSZ];

// ---------------------------------------------------------------------------
// Kernel 1: convert feats_s fp32 -> bf16
// ---------------------------------------------------------------------------
__global__ void k_convert(const float* __restrict__ fs) {
    int i = blockIdx.x * blockDim.x + threadIdx.x;    // float4 index, total NSUP*CDIM/4
    float4 v = ((const float4*)fs)[i];
    __nv_bfloat162 p0 = __floats2bfloat162_rn(v.x, v.y);
    __nv_bfloat162 p1 = __floats2bfloat162_rn(v.z, v.w);
    ((__nv_bfloat162*)g_fs_bf)[2 * i]     = p0;
    ((__nv_bfloat162*)g_fs_bf)[2 * i + 1] = p1;
}

// ---------------------------------------------------------------------------
// Kernel 2: tiled bf16 MMA + per-identity-block min/max reduction
// grid (MTILES, NSPLIT), 256 threads (8 warps: 4 along M x 2 along N)
// ---------------------------------------------------------------------------
extern __shared__ char smem_raw[];

__device__ __forceinline__ void mma16816(float* d, const uint32_t* a, uint32_t b0, uint32_t b1) {
    asm volatile(
        "mma.sync.aligned.m16n8k16.row.col.f32.bf16.bf16.f32 "
        "{%0,%1,%2,%3}, {%4,%5,%6,%7}, {%8,%9}, {%0,%1,%2,%3};\n"
        : "+f"(d[0]), "+f"(d[1]), "+f"(d[2]), "+f"(d[3])
        : "r"(a[0]), "r"(a[1]), "r"(a[2]), "r"(a[3]), "r"(b0), "r"(b1));
}

__global__ __launch_bounds__(256, 1) void k_main(const float* __restrict__ feats) {
    __nv_bfloat16* sA = (__nv_bfloat16*)smem_raw;                  // MTILE x SROW
    __nv_bfloat16* sB = sA + MTILE * SROW;                         // BLKC  x SROW
    float* sMax = (float*)(sB + BLKC * SROW);                      // MTILE x 2
    float* sMin = sMax + MTILE * 2;                                // MTILE x 2

    const int tid  = threadIdx.x;
    const int wid  = tid >> 5;
    const int lane = tid & 31;
    const int wm   = wid & 3;       // warp row (0..3) -> rows 32*wm..32*wm+31
    const int wn   = wid >> 2;      // warp col (0..1) -> cols 64*wn..64*wn+63
    const int g    = lane >> 2;
    const int q    = lane & 3;
    const int m0   = blockIdx.x * MTILE;
    const int split = blockIdx.y;
    const int jbase = split * BLOCKS_PER_SPLIT;

    // Load + convert feats tile to smem (bf16)
    for (int idx = tid; idx < MTILE * CDIM; idx += 256) {
        int r = idx >> 7, c = idx & 127;
        sA[r * SROW + c] = __float2bfloat16(feats[(size_t)(m0 + r) * CDIM + c]);
    }
    __syncthreads();

    // Preload all A fragments for this warp's 32 rows x K=128 into registers.
    uint32_t afr[2][8][4];
    {
        const int row_off = lane & 15;
        const int col_off = 8 * (lane >> 4);
#pragma unroll
        for (int mi = 0; mi < 2; mi++) {
            const int rm = 32 * wm + 16 * mi + row_off;
#pragma unroll
            for (int ks = 0; ks < 8; ks++) {
                uint32_t addr = (uint32_t)__cvta_generic_to_shared(&sA[rm * SROW + 16 * ks + col_off]);
                asm volatile("ldmatrix.sync.aligned.m8n8.x4.shared.b16 {%0,%1,%2,%3}, [%4];"
                             : "=r"(afr[mi][ks][0]), "=r"(afr[mi][ks][1]),
                               "=r"(afr[mi][ks][2]), "=r"(afr[mi][ks][3])
                             : "r"(addr));
            }
        }
    }

    // Per-n-fragment B smem pointers (conflict-free pattern: word = 4g+q mod 32)
    const __nv_bfloat16* bptr[8];
#pragma unroll
    for (int ni = 0; ni < 8; ni++)
        bptr[ni] = sB + (64 * wn + 8 * ni + g) * SROW + 2 * q;

    float negacc = 0.0f;
    float posval = 0.0f;

    for (int jb = 0; jb < BLOCKS_PER_SPLIT; ++jb) {
        const int j = jbase + jb;
        __syncthreads();   // sB free (previous compute + finalize done)

        // Stage identity block j of feats_s (bf16) into smem: 128 rows x 128 cols
        {
            const uint4* src = (const uint4*)(g_fs_bf + (size_t)j * BLKC * CDIM);
            for (int idx = tid; idx < (BLKC * CDIM) / 8; idx += 256) {   // 2048 uint4
                int r = idx >> 4, ch = idx & 15;
                *(uint4*)&sB[r * SROW + ch * 8] = src[idx];
            }
        }
        __syncthreads();

        float acc[2][8][4];
#pragma unroll
        for (int mi = 0; mi < 2; mi++)
#pragma unroll
            for (int ni = 0; ni < 8; ni++)
#pragma unroll
                for (int c = 0; c < 4; c++) acc[mi][ni][c] = 0.0f;

#pragma unroll
        for (int ks = 0; ks < 8; ks++) {
            const int kc = 16 * ks;
#pragma unroll
            for (int ni = 0; ni < 8; ni++) {
                uint32_t b0 = *(const uint32_t*)(bptr[ni] + kc);
                uint32_t b1 = *(const uint32_t*)(bptr[ni] + kc + 8);
                mma16816(acc[0][ni], afr[0][ks], b0, b1);
                mma16816(acc[1][ni], afr[1][ks], b0, b1);
            }
        }

        // Epilogue: per-row min/max over this block's 128 columns.
        // Thread owns rows {32wm+16mi+8h+g}; 16 col-values each (8 nfrag x 2).
#pragma unroll
        for (int mi = 0; mi < 2; mi++) {
#pragma unroll
            for (int h = 0; h < 2; h++) {
                float vmx = -1e30f, vmn = 1e30f;
#pragma unroll
                for (int ni = 0; ni < 8; ni++) {
                    float c0 = acc[mi][ni][2 * h];
                    float c1 = acc[mi][ni][2 * h + 1];
                    vmx = fmaxf(vmx, fmaxf(c0, c1));
                    vmn = fminf(vmn, fminf(c0, c1));
                }
                vmx = fmaxf(vmx, __shfl_xor_sync(0xFFFFFFFFu, vmx, 1));
                vmx = fmaxf(vmx, __shfl_xor_sync(0xFFFFFFFFu, vmx, 2));
                vmn = fminf(vmn, __shfl_xor_sync(0xFFFFFFFFu, vmn, 1));
                vmn = fminf(vmn, __shfl_xor_sync(0xFFFFFFFFu, vmn, 2));
                if (q == 0) {
                    int row = 32 * wm + 16 * mi + 8 * h + g;
                    sMax[row * 2 + wn] = vmx;
                    sMin[row * 2 + wn] = vmn;
                }
            }
        }
        __syncthreads();

        if (tid < MTILE) {
            float mx = fmaxf(sMax[tid * 2], sMax[tid * 2 + 1]);
            float mn = fminf(sMin[tid * 2], sMin[tid * 2 + 1]);
            int anchor = m0 + tid;
            if ((anchor >> 4) == j)                 // own identity block
                posval = expf(mn * INV_TEMP);       // min of exp == exp of min
            else
                negacc += expf(mx * INV_TEMP);      // max of exp == exp of max
        }
        // loop-top __syncthreads() protects sMax/sMin & sB reuse
    }

    if (tid < MTILE) {
        g_negpart[split * BSZ + m0 + tid] = negacc;
        g_pospart[split * BSZ + m0 + tid] = posval;
    }
}

// ---------------------------------------------------------------------------
// Kernel 3: combine splits, compute per-anchor loss, deterministic mean
// ---------------------------------------------------------------------------
__global__ void k_final(float* __restrict__ out) {
    __shared__ double red[256];
    int tid = threadIdx.x;
    double s = 0.0;
    for (int a = tid; a < BSZ; a += 256) {
        float neg = 0.0f, pos = 0.0f;
#pragma unroll
        for (int sp = 0; sp < NSPLIT; sp++) {
            neg += g_negpart[sp * BSZ + a];
            pos += g_pospart[sp * BSZ + a];
        }
        float loss = -logf(pos / (pos + neg + EPSV) + EPSV);
        s += (double)loss;
    }
    red[tid] = s;
    __syncthreads();
    for (int o = 128; o > 0; o >>= 1) {
        if (tid < o) red[tid] += red[tid + o];
        __syncthreads();
    }
    if (tid == 0) out[0] = (float)(red[0] / (double)BSZ);
}

// ---------------------------------------------------------------------------
// Launch
// ---------------------------------------------------------------------------
extern "C" void kernel_launch(void* const* d_in, const int* in_sizes, int n_in,
                              void* d_out, int out_size) {
    const float* feats   = (const float*)d_in[0];   // [4096,128] fp32
    const float* feats_s = (const float*)d_in[1];   // [4096,8,128] fp32
    float* out = (float*)d_out;

    const int smem_bytes = MTILE * SROW * 2 + BLKC * SROW * 2 + MTILE * 2 * 4 * 2; // ~71.7 KB
    cudaFuncSetAttribute(k_main, cudaFuncAttributeMaxDynamicSharedMemorySize, smem_bytes);

    k_convert<<<(NSUP * CDIM / 4) / 256, 256>>>(feats_s);
    dim3 grid(MTILES, NSPLIT);
    k_main<<<grid, 256, smem_bytes>>>(feats);
    k_final<<<1, 256>>>(out);
}

// round 2
// speedup vs baseline: 1.2491x; 1.2491x over previous
#include <cuda_runtime.h>
#include <cuda_bf16.h>
#include <cstdint>

// Problem constants
#define BSZ   4096
#define CDIM  128
#define TOPK  8
#define NSUP  (BSZ*TOPK)     // 32768 support rows
#define PIDS  256            // identity blocks
#define BLKC  128            // columns per identity block (K_INST*TOPK)
#define NSPLIT 4
#define BLOCKS_PER_SPLIT (PIDS/NSPLIT)   // 64
#define MTILE 128
#define MTILES (BSZ/MTILE)   // 32
#define INV_TEMP 20.0f
#define EPSV 1e-6f
#define SROW 136             // smem row stride in bf16 (128 + 8 pad, rows 16B-aligned, conflict-free)

// Scratch (static device globals: no allocation at runtime)
__device__ __nv_bfloat16 g_fs_bf[(size_t)NSUP * CDIM];       // 8 MB
__device__ float g_negpart[NSPLIT * BSZ];
__device__ float g_pospart[NSPLIT * BSZ];

// ---------------------------------------------------------------------------
// Kernel 1: convert feats_s fp32 -> bf16 (2 float4 per thread)
// ---------------------------------------------------------------------------
__global__ void k_convert(const float* __restrict__ fs) {
    int i = (blockIdx.x * blockDim.x + threadIdx.x) * 2;    // float4 index
    float4 v0 = ((const float4*)fs)[i];
    float4 v1 = ((const float4*)fs)[i + 1];
    __nv_bfloat162* dst = (__nv_bfloat162*)g_fs_bf;
    dst[2 * i]     = __floats2bfloat162_rn(v0.x, v0.y);
    dst[2 * i + 1] = __floats2bfloat162_rn(v0.z, v0.w);
    dst[2 * i + 2] = __floats2bfloat162_rn(v1.x, v1.y);
    dst[2 * i + 3] = __floats2bfloat162_rn(v1.z, v1.w);
}

// ---------------------------------------------------------------------------
// cp.async helpers
// ---------------------------------------------------------------------------
__device__ __forceinline__ void cp_async16(uint32_t smem_addr, const void* gptr) {
    asm volatile("cp.async.cg.shared.global [%0], [%1], 16;\n"
                 :: "r"(smem_addr), "l"(gptr));
}
__device__ __forceinline__ void cp_commit() {
    asm volatile("cp.async.commit_group;\n");
}
template <int N>
__device__ __forceinline__ void cp_wait() {
    asm volatile("cp.async.wait_group %0;\n" :: "n"(N));
}

__device__ __forceinline__ void mma16816(float* d, const uint32_t* a, uint32_t b0, uint32_t b1) {
    asm volatile(
        "mma.sync.aligned.m16n8k16.row.col.f32.bf16.bf16.f32 "
        "{%0,%1,%2,%3}, {%4,%5,%6,%7}, {%8,%9}, {%0,%1,%2,%3};\n"
        : "+f"(d[0]), "+f"(d[1]), "+f"(d[2]), "+f"(d[3])
        : "r"(a[0]), "r"(a[1]), "r"(a[2]), "r"(a[3]), "r"(b0), "r"(b1));
}

// ---------------------------------------------------------------------------
// Kernel 2: tiled bf16 MMA + per-identity-block min/max reduction
// grid (MTILES, NSPLIT), 256 threads (8 warps: 4 along M x 2 along N)
// 2-stage cp.async double-buffered B pipeline.
// ---------------------------------------------------------------------------
extern __shared__ char smem_raw[];

__global__ __launch_bounds__(256, 1) void k_main(const float* __restrict__ feats) {
    __nv_bfloat16* sA = (__nv_bfloat16*)smem_raw;                  // MTILE x SROW
    __nv_bfloat16* sB = sA + MTILE * SROW;                         // 2 x BLKC x SROW
    float* sMax = (float*)(sB + 2 * BLKC * SROW);                  // MTILE x 2
    float* sMin = sMax + MTILE * 2;                                // MTILE x 2

    const int tid  = threadIdx.x;
    const int wid  = tid >> 5;
    const int lane = tid & 31;
    const int wm   = wid & 3;       // warp row (0..3) -> rows 32*wm..32*wm+31
    const int wn   = wid >> 2;      // warp col (0..1) -> cols 64*wn..64*wn+63
    const int g    = lane >> 2;
    const int q    = lane & 3;
    const int m0   = blockIdx.x * MTILE;
    const int split = blockIdx.y;
    const int jbase = split * BLOCKS_PER_SPLIT;

    // Issue async load of B block 0 into buffer 0 FIRST (gets L2 traffic in flight)
    auto issueB = [&](int j, int buf) {
        const char* src = (const char*)(g_fs_bf + (size_t)j * BLKC * CDIM);
        __nv_bfloat16* dstb = sB + buf * BLKC * SROW;
        #pragma unroll
        for (int it = 0; it < 8; it++) {
            int idx = tid + it * 256;                // 0..2047
            int r = idx >> 4, ch = idx & 15;
            uint32_t da = (uint32_t)__cvta_generic_to_shared(dstb + r * SROW + ch * 8);
            cp_async16(da, src + (size_t)idx * 16);
        }
        cp_commit();
    };
    issueB(jbase, 0);

    // Load + convert feats tile to smem (bf16)
    for (int idx = tid; idx < MTILE * CDIM; idx += 256) {
        int r = idx >> 7, c = idx & 127;
        sA[r * SROW + c] = __float2bfloat16(feats[(size_t)(m0 + r) * CDIM + c]);
    }
    __syncthreads();

    // Preload all A fragments for this warp's 32 rows x K=128 into registers.
    uint32_t afr[2][8][4];
    {
        const int row_off = lane & 15;
        const int col_off = 8 * (lane >> 4);
#pragma unroll
        for (int mi = 0; mi < 2; mi++) {
            const int rm = 32 * wm + 16 * mi + row_off;
#pragma unroll
            for (int ks = 0; ks < 8; ks++) {
                uint32_t addr = (uint32_t)__cvta_generic_to_shared(&sA[rm * SROW + 16 * ks + col_off]);
                asm volatile("ldmatrix.sync.aligned.m8n8.x4.shared.b16 {%0,%1,%2,%3}, [%4];"
                             : "=r"(afr[mi][ks][0]), "=r"(afr[mi][ks][1]),
                               "=r"(afr[mi][ks][2]), "=r"(afr[mi][ks][3])
                             : "r"(addr));
            }
        }
    }

    // Per-n-fragment B smem base offsets (conflict-free: word = 4g+q mod 32)
    const __nv_bfloat16* bptr[8];
#pragma unroll
    for (int ni = 0; ni < 8; ni++)
        bptr[ni] = sB + (64 * wn + 8 * ni + g) * SROW + 2 * q;

    float negacc = 0.0f;
    float posval = 0.0f;

    for (int jb = 0; jb < BLOCKS_PER_SPLIT; ++jb) {
        const int buf = jb & 1;
        // Prefetch next block into the other buffer (safe: all reads of that
        // buffer completed before the epilogue barrier of iter jb-1).
        if (jb + 1 < BLOCKS_PER_SPLIT) {
            issueB(jbase + jb + 1, buf ^ 1);
            cp_wait<1>();          // block jb's group complete (this thread)
        } else {
            cp_wait<0>();
        }
        __syncthreads();           // all threads' cp.async data visible

        const int boff = buf * BLKC * SROW;

        float acc[2][8][4];
#pragma unroll
        for (int mi = 0; mi < 2; mi++)
#pragma unroll
            for (int ni = 0; ni < 8; ni++)
#pragma unroll
                for (int c = 0; c < 4; c++) acc[mi][ni][c] = 0.0f;

#pragma unroll
        for (int ks = 0; ks < 8; ks++) {
            const int kc = 16 * ks;
#pragma unroll
            for (int ni = 0; ni < 8; ni++) {
                uint32_t b0 = *(const uint32_t*)(bptr[ni] + boff + kc);
                uint32_t b1 = *(const uint32_t*)(bptr[ni] + boff + kc + 8);
                mma16816(acc[0][ni], afr[0][ks], b0, b1);
                mma16816(acc[1][ni], afr[1][ks], b0, b1);
            }
        }

        // Epilogue: per-row min/max over this block's 128 columns.
#pragma unroll
        for (int mi = 0; mi < 2; mi++) {
#pragma unroll
            for (int h = 0; h < 2; h++) {
                float vmx = -1e30f, vmn = 1e30f;
#pragma unroll
                for (int ni = 0; ni < 8; ni++) {
                    float c0 = acc[mi][ni][2 * h];
                    float c1 = acc[mi][ni][2 * h + 1];
                    vmx = fmaxf(vmx, fmaxf(c0, c1));
                    vmn = fminf(vmn, fminf(c0, c1));
                }
                vmx = fmaxf(vmx, __shfl_xor_sync(0xFFFFFFFFu, vmx, 1));
                vmx = fmaxf(vmx, __shfl_xor_sync(0xFFFFFFFFu, vmx, 2));
                vmn = fminf(vmn, __shfl_xor_sync(0xFFFFFFFFu, vmn, 1));
                vmn = fminf(vmn, __shfl_xor_sync(0xFFFFFFFFu, vmn, 2));
                if (q == 0) {
                    int row = 32 * wm + 16 * mi + 8 * h + g;
                    sMax[row * 2 + wn] = vmx;
                    sMin[row * 2 + wn] = vmn;
                }
            }
        }
        __syncthreads();

        if (tid < MTILE) {
            float mx = fmaxf(sMax[tid * 2], sMax[tid * 2 + 1]);
            float mn = fminf(sMin[tid * 2], sMin[tid * 2 + 1]);
            int anchor = m0 + tid;
            if ((anchor >> 4) == (jbase + jb))       // own identity block
                posval = expf(mn * INV_TEMP);        // min of exp == exp of min
            else
                negacc += expf(mx * INV_TEMP);       // max of exp == exp of max
        }
        // next iter's wait+syncthreads orders sMax reads vs. rewrites
    }

    if (tid < MTILE) {
        g_negpart[split * BSZ + m0 + tid] = negacc;
        g_pospart[split * BSZ + m0 + tid] = posval;
    }
}

// ---------------------------------------------------------------------------
// Kernel 3: combine splits, per-anchor loss, deterministic mean
// ---------------------------------------------------------------------------
__global__ void k_final(float* __restrict__ out) {
    __shared__ double red[256];
    int tid = threadIdx.x;
    double s = 0.0;
    for (int a = tid; a < BSZ; a += 256) {
        float neg = 0.0f, pos = 0.0f;
#pragma unroll
        for (int sp = 0; sp < NSPLIT; sp++) {
            neg += g_negpart[sp * BSZ + a];
            pos += g_pospart[sp * BSZ + a];
        }
        float loss = -logf(pos / (pos + neg + EPSV) + EPSV);
        s += (double)loss;
    }
    red[tid] = s;
    __syncthreads();
    for (int o = 128; o > 0; o >>= 1) {
        if (tid < o) red[tid] += red[tid + o];
        __syncthreads();
    }
    if (tid == 0) out[0] = (float)(red[0] / (double)BSZ);
}

// ---------------------------------------------------------------------------
// Launch
// ---------------------------------------------------------------------------
extern "C" void kernel_launch(void* const* d_in, const int* in_sizes, int n_in,
                              void* d_out, int out_size) {
    const float* feats   = (const float*)d_in[0];   // [4096,128] fp32
    const float* feats_s = (const float*)d_in[1];   // [4096,8,128] fp32
    float* out = (float*)d_out;

    const int smem_bytes = MTILE * SROW * 2 + 2 * BLKC * SROW * 2 + MTILE * 2 * 4 * 2; // ~107 KB
    cudaFuncSetAttribute(k_main, cudaFuncAttributeMaxDynamicSharedMemorySize, smem_bytes);

    k_convert<<<(NSUP * CDIM / 8) / 256, 256>>>(feats_s);
    dim3 grid(MTILES, NSPLIT);
    k_main<<<grid, 256, smem_bytes>>>(feats);
    k_final<<<1, 256>>>(out);
}

// round 4
// speedup vs baseline: 1.3627x; 1.0909x over previous
#include <cuda_runtime.h>
#include <cuda_bf16.h>
#include <cstdint>

// Problem constants
#define BSZ   4096
#define CDIM  128
#define NSUP  32768          // 4096*8 support rows
#define PIDS  256
#define BLKC  128            // columns per identity block
#define NSPLIT 8
#define BPS   (PIDS/NSPLIT)  // 32 blocks per split
#define MTILE 128
#define MTILES (BSZ/MTILE)   // 32
#define INV_TEMP 20.0f
#define EPSV 1e-6f
#define SROW 136             // smem row stride in bf16 (128+8 pad, conflict-free)

// Scratch (static device globals)
__device__ __nv_bfloat16 g_fs_bf[(size_t)NSUP * CDIM];   // 8 MB
__device__ float g_negpart[NSPLIT * BSZ];
__device__ float g_pospart[NSPLIT * BSZ];

// ---------------------------------------------------------------------------
// Kernel 1: convert feats_s fp32 -> bf16 (2 float4 per thread)
// ---------------------------------------------------------------------------
__global__ void k_convert(const float* __restrict__ fs) {
    int i = (blockIdx.x * blockDim.x + threadIdx.x) * 2;    // float4 index
    float4 v0 = ((const float4*)fs)[i];
    float4 v1 = ((const float4*)fs)[i + 1];
    __nv_bfloat162* dst = (__nv_bfloat162*)g_fs_bf;
    dst[2 * i]     = __floats2bfloat162_rn(v0.x, v0.y);
    dst[2 * i + 1] = __floats2bfloat162_rn(v0.z, v0.w);
    dst[2 * i + 2] = __floats2bfloat162_rn(v1.x, v1.y);
    dst[2 * i + 3] = __floats2bfloat162_rn(v1.z, v1.w);
}

// ---------------------------------------------------------------------------
// Helpers
// ---------------------------------------------------------------------------
__device__ __forceinline__ void cp_async16(uint32_t smem_addr, const void* gptr) {
    asm volatile("cp.async.cg.shared.global [%0], [%1], 16;\n"
                 :: "r"(smem_addr), "l"(gptr));
}
__device__ __forceinline__ void cp_commit() { asm volatile("cp.async.commit_group;\n"); }
template <int N> __device__ __forceinline__ void cp_wait() {
    asm volatile("cp.async.wait_group %0;\n" :: "n"(N));
}

__device__ __forceinline__ void mma16816(float* d, const uint32_t* a, uint32_t b0, uint32_t b1) {
    asm volatile(
        "mma.sync.aligned.m16n8k16.row.col.f32.bf16.bf16.f32 "
        "{%0,%1,%2,%3}, {%4,%5,%6,%7}, {%8,%9}, {%0,%1,%2,%3};\n"
        : "+f"(d[0]), "+f"(d[1]), "+f"(d[2]), "+f"(d[3])
        : "r"(a[0]), "r"(a[1]), "r"(a[2]), "r"(a[3]), "r"(b0), "r"(b1));
}

// ---------------------------------------------------------------------------
// Kernel 2: tiled bf16 MMA + per-identity-block min/max reduction
// grid (MTILES, NSPLIT) = 256 CTAs, 256 threads, 2 CTAs/SM.
// Warps: 4 along M x 2 along N. N accumulated in two 64-col passes
// (register pressure: fits 128 regs for occupancy 2).
// ---------------------------------------------------------------------------
extern __shared__ char smem_raw[];

__global__ __launch_bounds__(256, 2) void k_main(const float* __restrict__ feats) {
    __nv_bfloat16* sA = (__nv_bfloat16*)smem_raw;                  // MTILE x SROW
    __nv_bfloat16* sB = sA + MTILE * SROW;                         // 2 x BLKC x SROW
    float* sMax = (float*)(sB + 2 * BLKC * SROW);                  // MTILE x 2
    float* sMin = sMax + MTILE * 2;                                // MTILE x 2

    const int tid  = threadIdx.x;
    const int wid  = tid >> 5;
    const int lane = tid & 31;
    const int wm   = wid & 3;       // warp row (0..3)
    const int wn   = wid >> 2;      // warp col (0..1)
    const int g    = lane >> 2;
    const int q    = lane & 3;
    const int m0   = blockIdx.x * MTILE;
    const int split = blockIdx.y;
    const int jbase = split * BPS;

    auto issueB = [&](int j, int buf) {
        const char* src = (const char*)(g_fs_bf + (size_t)j * BLKC * CDIM);
        __nv_bfloat16* dstb = sB + buf * BLKC * SROW;
        #pragma unroll
        for (int it = 0; it < 8; it++) {
            int idx = tid + it * 256;                // 0..2047
            int r = idx >> 4, ch = idx & 15;
            uint32_t da = (uint32_t)__cvta_generic_to_shared(dstb + r * SROW + ch * 8);
            cp_async16(da, src + (size_t)idx * 16);
        }
        cp_commit();
    };
    issueB(jbase, 0);

    // feats tile -> bf16 smem
    for (int idx = tid; idx < MTILE * CDIM; idx += 256) {
        int r = idx >> 7, c = idx & 127;
        sA[r * SROW + c] = __float2bfloat16(feats[(size_t)(m0 + r) * CDIM + c]);
    }
    __syncthreads();

    // Preload A fragments: 32 rows x K=128 per warp (64 regs)
    uint32_t afr[2][8][4];
    {
        const int row_off = lane & 15;
        const int col_off = 8 * (lane >> 4);
#pragma unroll
        for (int mi = 0; mi < 2; mi++) {
            const int rm = 32 * wm + 16 * mi + row_off;
#pragma unroll
            for (int ks = 0; ks < 8; ks++) {
                uint32_t addr = (uint32_t)__cvta_generic_to_shared(&sA[rm * SROW + 16 * ks + col_off]);
                asm volatile("ldmatrix.sync.aligned.m8n8.x4.shared.b16 {%0,%1,%2,%3}, [%4];"
                             : "=r"(afr[mi][ks][0]), "=r"(afr[mi][ks][1]),
                               "=r"(afr[mi][ks][2]), "=r"(afr[mi][ks][3])
                             : "r"(addr));
            }
        }
    }

    // B fragment offsets (bf16 elements from sB): conflict-free (word = 4g+q mod 32)
    uint32_t boff[8];
#pragma unroll
    for (int ni = 0; ni < 8; ni++)
        boff[ni] = (uint32_t)((64 * wn + 8 * ni + g) * SROW + 2 * q);

    float negacc = 0.0f;
    float posval = 0.0f;

    for (int jb = 0; jb < BPS; ++jb) {
        const int buf = jb & 1;
        if (jb + 1 < BPS) { issueB(jbase + jb + 1, buf ^ 1); cp_wait<1>(); }
        else              { cp_wait<0>(); }
        __syncthreads();

        const __nv_bfloat16* bbase = sB + buf * BLKC * SROW;

        float vmx[2][2], vmn[2][2];
#pragma unroll
        for (int p = 0; p < 2; p++) {          // two 64-col N passes
            float acc[2][4][4];
#pragma unroll
            for (int mi = 0; mi < 2; mi++)
#pragma unroll
                for (int n4 = 0; n4 < 4; n4++)
#pragma unroll
                    for (int c = 0; c < 4; c++) acc[mi][n4][c] = 0.0f;

#pragma unroll
            for (int ks = 0; ks < 8; ks++) {
                const int kc = 16 * ks;
#pragma unroll
                for (int n4 = 0; n4 < 4; n4++) {
                    const __nv_bfloat16* bp = bbase + boff[4 * p + n4];
                    uint32_t b0 = *(const uint32_t*)(bp + kc);
                    uint32_t b1 = *(const uint32_t*)(bp + kc + 8);
                    mma16816(acc[0][n4], afr[0][ks], b0, b1);
                    mma16816(acc[1][n4], afr[1][ks], b0, b1);
                }
            }
            // fold this pass's 8 col-values per row into running partials
#pragma unroll
            for (int mi = 0; mi < 2; mi++) {
#pragma unroll
                for (int h = 0; h < 2; h++) {
                    float mx = -1e30f, mn = 1e30f;
#pragma unroll
                    for (int n4 = 0; n4 < 4; n4++) {
                        float c0 = acc[mi][n4][2 * h];
                        float c1 = acc[mi][n4][2 * h + 1];
                        mx = fmaxf(mx, fmaxf(c0, c1));
                        mn = fminf(mn, fminf(c0, c1));
                    }
                    if (p == 0) { vmx[mi][h] = mx; vmn[mi][h] = mn; }
                    else { vmx[mi][h] = fmaxf(vmx[mi][h], mx); vmn[mi][h] = fminf(vmn[mi][h], mn); }
                }
            }
        }

        // cross-lane (q) reduce + smem
#pragma unroll
        for (int mi = 0; mi < 2; mi++) {
#pragma unroll
            for (int h = 0; h < 2; h++) {
                float mx = vmx[mi][h], mn = vmn[mi][h];
                mx = fmaxf(mx, __shfl_xor_sync(0xFFFFFFFFu, mx, 1));
                mx = fmaxf(mx, __shfl_xor_sync(0xFFFFFFFFu, mx, 2));
                mn = fminf(mn, __shfl_xor_sync(0xFFFFFFFFu, mn, 1));
                mn = fminf(mn, __shfl_xor_sync(0xFFFFFFFFu, mn, 2));
                if (q == 0) {
                    int row = 32 * wm + 16 * mi + 8 * h + g;
                    sMax[row * 2 + wn] = mx;
                    sMin[row * 2 + wn] = mn;
                }
            }
        }
        __syncthreads();

        if (tid < MTILE) {
            float mx = fmaxf(sMax[tid * 2], sMax[tid * 2 + 1]);
            float mn = fminf(sMin[tid * 2], sMin[tid * 2 + 1]);
            int anchor = m0 + tid;
            if ((anchor >> 4) == (jbase + jb))       // own identity block
                posval = expf(mn * INV_TEMP);        // min of exp == exp of min
            else
                negacc += expf(mx * INV_TEMP);       // max of exp == exp of max
        }
        // next iter's wait+syncthreads orders sMax reads vs. rewrites
    }

    if (tid < MTILE) {
        g_negpart[split * BSZ + m0 + tid] = negacc;
        g_pospart[split * BSZ + m0 + tid] = posval;
    }
}

// ---------------------------------------------------------------------------
// Kernel 3: combine splits, per-anchor loss, deterministic mean
// ---------------------------------------------------------------------------
__global__ void k_final(float* __restrict__ out) {
    __shared__ double red[256];
    int tid = threadIdx.x;
    double s = 0.0;
    for (int a = tid; a < BSZ; a += 256) {
        float neg = 0.0f, pos = 0.0f;
#pragma unroll
        for (int sp = 0; sp < NSPLIT; sp++) {
            neg += g_negpart[sp * BSZ + a];
            pos += g_pospart[sp * BSZ + a];
        }
        float loss = -logf(pos / (pos + neg + EPSV) + EPSV);
        s += (double)loss;
    }
    red[tid] = s;
    __syncthreads();
    for (int o = 128; o > 0; o >>= 1) {
        if (tid < o) red[tid] += red[tid + o];
        __syncthreads();
    }
    if (tid == 0) out[0] = (float)(red[0] / (double)BSZ);
}

// ---------------------------------------------------------------------------
// Launch
// ---------------------------------------------------------------------------
extern "C" void kernel_launch(void* const* d_in, const int* in_sizes, int n_in,
                              void* d_out, int out_size) {
    const float* feats   = (const float*)d_in[0];   // [4096,128] fp32
    const float* feats_s = (const float*)d_in[1];   // [4096,8,128] fp32
    float* out = (float*)d_out;

    // A (34816) + 2xB (69632) + reduce scratch (2048) = 106496 B; 2 CTAs/SM fit 228KB
    const int smem_bytes = MTILE * SROW * 2 + 2 * BLKC * SROW * 2 + MTILE * 2 * 4 * 2;
    cudaFuncSetAttribute(k_main, cudaFuncAttributeMaxDynamicSharedMemorySize, smem_bytes);

    k_convert<<<(NSUP * CDIM / 8) / 256, 256>>>(feats_s);
    dim3 grid(MTILES, NSPLIT);
    k_main<<<grid, 256, smem_bytes>>>(feats);
    k_final<<<1, 256>>>(out);
}